// round 9
// baseline (speedup 1.0000x reference)
#include <cuda_runtime.h>
#include <math.h>

// ---------------------------------------------------------------------------
// TransformerCell: out = LN(relu(MHA(q=h, kv=concat(c,h,e,s), 8 heads)))
// Factorized exact algebra:
//   qp   = (h @ Wq^T + bq) / 8                      [N,512]
//   qt_h = Wk_h^T qp_h                              [N,8,512]  (q.bk const -> drops)
//   s_hj = qt_h . ctx_j ; attn = softmax_j          per (n,h), 35 ctx rows
//   w_h  = sum_j attn_j * ctx_j                     [N,8,512]
//   o_h  = Wv_h w_h + bv_h                          [N,512]   (sum attn = 1)
//   y    = o @ Wo^T + bo ; out = LN(relu(y))  (std ddof=1, eps added to std)
// ---------------------------------------------------------------------------

#define NB    8192
#define DIM   512
#define HEADS 8
#define KCTX  35

__device__ __align__(16) float g_q [NB * DIM];          // 16 MB
__device__ __align__(16) float g_qt[NB * HEADS * DIM];  // 128 MB
__device__ __align__(16) float g_w [NB * HEADS * DIM];  // 128 MB
__device__ __align__(16) float g_o [NB * DIM];          // 16 MB
__device__ __align__(16) float g_y [NB * DIM];          // 16 MB

// ---------------------------------------------------------------------------
// fp32 GEMM, BM=128, BN=64, BK=16, 256 threads, 8x4 register tile.
// BT=true : C[m][n] = (sum_k A[m][k]*B[n][k] + bias[n]) * alpha   (B is NxK)
// BT=false: C[m][n] = (sum_k A[m][k]*B[k][n] + bias[n]) * alpha   (B is KxN)
// blockIdx.z selects a batch (head) via element offsets {a,b,c,bias}Batch.
// All dims are exact multiples of the tile for this problem; no edge guards.
// ---------------------------------------------------------------------------
template <bool BT>
__global__ void __launch_bounds__(256)
gemm128x64(const float* __restrict__ A, int lda, int aBatch,
           const float* __restrict__ B, int ldb, int bBatch,
           const float* __restrict__ bias, int biasBatch,
           float* __restrict__ C, int ldc, int cBatch,
           int K, float alpha)
{
    __shared__ float As[16][128];
    __shared__ float Bs[16][64];

    A += (long)blockIdx.z * aBatch;
    B += (long)blockIdx.z * bBatch;
    C += (long)blockIdx.z * cBatch;
    const float* bptr = bias ? (bias + (long)blockIdx.z * biasBatch) : (const float*)0;

    const int bm  = blockIdx.y * 128;
    const int bn  = blockIdx.x * 64;
    const int tid = threadIdx.x;

    const int trow = (tid >> 4) * 8;   // 0..120 step 8
    const int tcol = (tid & 15) * 4;   // 0..60  step 4

    float acc[8][4];
#pragma unroll
    for (int i = 0; i < 8; i++)
#pragma unroll
        for (int j = 0; j < 4; j++) acc[i][j] = 0.f;

    const int arow = tid >> 1;          // 0..127
    const int akq  = (tid & 1) * 8;     // 0 or 8
    const float* aBase = A + (long)(bm + arow) * lda + akq;

    for (int k0 = 0; k0 < K; k0 += 16) {
        float4 a0 = *(const float4*)(aBase + k0);
        float4 a1 = *(const float4*)(aBase + k0 + 4);
        As[akq + 0][arow] = a0.x; As[akq + 1][arow] = a0.y;
        As[akq + 2][arow] = a0.z; As[akq + 3][arow] = a0.w;
        As[akq + 4][arow] = a1.x; As[akq + 5][arow] = a1.y;
        As[akq + 6][arow] = a1.z; As[akq + 7][arow] = a1.w;

        if (BT) {
            const int brow = tid >> 2;        // 0..63  (n)
            const int bkq  = (tid & 3) * 4;   // 0..12  (k)
            float4 v = *(const float4*)(B + (long)(bn + brow) * ldb + k0 + bkq);
            Bs[bkq + 0][brow] = v.x; Bs[bkq + 1][brow] = v.y;
            Bs[bkq + 2][brow] = v.z; Bs[bkq + 3][brow] = v.w;
        } else {
            const int bkk = tid >> 4;         // 0..15  (k)
            const int bnn = (tid & 15) * 4;   // 0..60  (n)
            *(float4*)&Bs[bkk][bnn] =
                *(const float4*)(B + (long)(k0 + bkk) * ldb + bn + bnn);
        }
        __syncthreads();

#pragma unroll
        for (int k = 0; k < 16; k++) {
            float a[8], bb[4];
            *(float4*)&a[0] = *(const float4*)&As[k][trow];
            *(float4*)&a[4] = *(const float4*)&As[k][trow + 4];
            *(float4*)&bb[0] = *(const float4*)&Bs[k][tcol];
#pragma unroll
            for (int i = 0; i < 8; i++)
#pragma unroll
                for (int j = 0; j < 4; j++) acc[i][j] = fmaf(a[i], bb[j], acc[i][j]);
        }
        __syncthreads();
    }

    float bvals[4] = {0.f, 0.f, 0.f, 0.f};
    if (bptr) {
#pragma unroll
        for (int j = 0; j < 4; j++) bvals[j] = bptr[bn + tcol + j];
    }
#pragma unroll
    for (int i = 0; i < 8; i++) {
        float4 outv;
        outv.x = (acc[i][0] + bvals[0]) * alpha;
        outv.y = (acc[i][1] + bvals[1]) * alpha;
        outv.z = (acc[i][2] + bvals[2]) * alpha;
        outv.w = (acc[i][3] + bvals[3]) * alpha;
        *(float4*)(C + (long)(bm + trow + i) * ldc + bn + tcol) = outv;
    }
}

// ---------------------------------------------------------------------------
// Attention core: one CTA per batch n, 256 threads = 8 warps.
//  Phase B: warp (hp,jg) -> heads {2hp,2hp+1}, j-half   (qt in regs, ctx stream)
//  Softmax: warp h -> head h (35 scores across lanes)
//  Phase C: warp (hp,dh) -> heads {2hp,2hp+1}, 256-d half (w accumulated in regs)
// ctx rows read directly from gmem (coalesced float4); 70 KB set lives in L1.
// ---------------------------------------------------------------------------
__global__ void __launch_bounds__(256)
attn_core(const float* __restrict__ qt, const float* __restrict__ cc,
          const float* __restrict__ hv, const float* __restrict__ ev,
          const float* __restrict__ sv, float* __restrict__ wout)
{
    __shared__ const float* ptrs[KCTX];
    __shared__ float sc[HEADS][KCTX];
    __shared__ float attnw[HEADS][KCTX];

    const int n    = blockIdx.x;
    const int tid  = threadIdx.x;
    const int lane = tid & 31;
    const int warp = tid >> 5;

    if (tid < KCTX) {
        const float* p;
        if (tid < 32)       p = cc + ((long)n * 32 + tid) * DIM;
        else if (tid == 32) p = hv + (long)n * DIM;
        else if (tid == 33) p = ev + (long)n * DIM;
        else                p = sv + (long)n * DIM;
        ptrs[tid] = p;
    }
    __syncthreads();

    const int hp = warp >> 1;
    const int h0 = hp * 2, h1 = h0 + 1;

    // ---- Phase B: scores ---------------------------------------------------
    {
        const float4* qa = (const float4*)(qt + (long)n * (HEADS * DIM) + h0 * DIM);
        const float4* qb = (const float4*)(qt + (long)n * (HEADS * DIM) + h1 * DIM);
        float4 ra[4], rb[4];
#pragma unroll
        for (int i = 0; i < 4; i++) { ra[i] = qa[lane + 32 * i]; rb[i] = qb[lane + 32 * i]; }

        const int jg = warp & 1;
        const int jb = jg ? 18 : 0;
        const int je = jg ? KCTX : 18;
        for (int j = jb; j < je; j++) {
            const float4* xp = (const float4*)ptrs[j];
            float p0 = 0.f, p1 = 0.f;
#pragma unroll
            for (int i = 0; i < 4; i++) {
                float4 x = xp[lane + 32 * i];
                p0 = fmaf(ra[i].x, x.x, p0); p0 = fmaf(ra[i].y, x.y, p0);
                p0 = fmaf(ra[i].z, x.z, p0); p0 = fmaf(ra[i].w, x.w, p0);
                p1 = fmaf(rb[i].x, x.x, p1); p1 = fmaf(rb[i].y, x.y, p1);
                p1 = fmaf(rb[i].z, x.z, p1); p1 = fmaf(rb[i].w, x.w, p1);
            }
#pragma unroll
            for (int o = 16; o; o >>= 1) {
                p0 += __shfl_xor_sync(0xffffffffu, p0, o);
                p1 += __shfl_xor_sync(0xffffffffu, p1, o);
            }
            if (lane == 0) { sc[h0][j] = p0; sc[h1][j] = p1; }
        }
    }
    __syncthreads();

    // ---- Softmax (warp = head) ----------------------------------------------
    {
        const int hh = warp;
        float s1 = sc[hh][lane];
        float s2 = (lane < 3) ? sc[hh][32 + lane] : -3.0e38f;
        float m = fmaxf(s1, s2);
#pragma unroll
        for (int o = 16; o; o >>= 1)
            m = fmaxf(m, __shfl_xor_sync(0xffffffffu, m, o));
        float e1 = expf(s1 - m);
        float e2 = (lane < 3) ? expf(s2 - m) : 0.f;
        float sum = e1 + e2;
#pragma unroll
        for (int o = 16; o; o >>= 1)
            sum += __shfl_xor_sync(0xffffffffu, sum, o);
        float inv = 1.f / sum;
        attnw[hh][lane] = e1 * inv;
        if (lane < 3) attnw[hh][32 + lane] = e2 * inv;
    }
    __syncthreads();

    // ---- Phase C: w = attn @ ctx --------------------------------------------
    {
        const int dh    = warp & 1;
        const int dbase = dh * 256;            // floats
        float4 acc[2][2];
#pragma unroll
        for (int hI = 0; hI < 2; hI++)
#pragma unroll
            for (int i = 0; i < 2; i++)
                acc[hI][i] = make_float4(0.f, 0.f, 0.f, 0.f);

        for (int j = 0; j < KCTX; j++) {
            const float4* xp = (const float4*)(ptrs[j] + dbase);
            float a0 = attnw[h0][j];
            float a1 = attnw[h1][j];
#pragma unroll
            for (int i = 0; i < 2; i++) {
                float4 x = xp[lane + 32 * i];
                acc[0][i].x = fmaf(a0, x.x, acc[0][i].x);
                acc[0][i].y = fmaf(a0, x.y, acc[0][i].y);
                acc[0][i].z = fmaf(a0, x.z, acc[0][i].z);
                acc[0][i].w = fmaf(a0, x.w, acc[0][i].w);
                acc[1][i].x = fmaf(a1, x.x, acc[1][i].x);
                acc[1][i].y = fmaf(a1, x.y, acc[1][i].y);
                acc[1][i].z = fmaf(a1, x.z, acc[1][i].z);
                acc[1][i].w = fmaf(a1, x.w, acc[1][i].w);
            }
        }
        float4* w0 = (float4*)(wout + (long)n * (HEADS * DIM) + h0 * DIM + dbase);
        float4* w1 = (float4*)(wout + (long)n * (HEADS * DIM) + h1 * DIM + dbase);
#pragma unroll
        for (int i = 0; i < 2; i++) {
            w0[lane + 32 * i] = acc[0][i];
            w1[lane + 32 * i] = acc[1][i];
        }
    }
}

// ---------------------------------------------------------------------------
// relu + LayerNorm (ddof=1, eps added to STD). One warp per row.
// ---------------------------------------------------------------------------
__global__ void __launch_bounds__(256)
relu_ln(const float* __restrict__ y, const float* __restrict__ ln_a,
        const float* __restrict__ ln_b, float* __restrict__ out)
{
    const int lane = threadIdx.x & 31;
    const int warp = threadIdx.x >> 5;
    const int row  = blockIdx.x * 8 + warp;

    const float4* xr = (const float4*)(y + (long)row * DIM);
    float4 v[4];
    float sum = 0.f;
#pragma unroll
    for (int i = 0; i < 4; i++) {
        float4 x = xr[lane + 32 * i];
        x.x = fmaxf(x.x, 0.f); x.y = fmaxf(x.y, 0.f);
        x.z = fmaxf(x.z, 0.f); x.w = fmaxf(x.w, 0.f);
        v[i] = x;
        sum += x.x + x.y + x.z + x.w;
    }
#pragma unroll
    for (int o = 16; o; o >>= 1) sum += __shfl_xor_sync(0xffffffffu, sum, o);
    const float mean = sum * (1.f / (float)DIM);

    float ssq = 0.f;
#pragma unroll
    for (int i = 0; i < 4; i++) {
        float dx;
        dx = v[i].x - mean; ssq = fmaf(dx, dx, ssq);
        dx = v[i].y - mean; ssq = fmaf(dx, dx, ssq);
        dx = v[i].z - mean; ssq = fmaf(dx, dx, ssq);
        dx = v[i].w - mean; ssq = fmaf(dx, dx, ssq);
    }
#pragma unroll
    for (int o = 16; o; o >>= 1) ssq += __shfl_xor_sync(0xffffffffu, ssq, o);
    const float stddev = sqrtf(ssq * (1.f / (float)(DIM - 1)));
    const float inv = 1.f / (stddev + 1e-6f);

    float4* orow = (float4*)(out + (long)row * DIM);
    const float4* a4 = (const float4*)ln_a;
    const float4* b4 = (const float4*)ln_b;
#pragma unroll
    for (int i = 0; i < 4; i++) {
        const int idx = lane + 32 * i;
        float4 a = a4[idx], b = b4[idx], o4;
        o4.x = fmaf(a.x * inv, v[i].x - mean, b.x);
        o4.y = fmaf(a.y * inv, v[i].y - mean, b.y);
        o4.z = fmaf(a.z * inv, v[i].z - mean, b.z);
        o4.w = fmaf(a.w * inv, v[i].w - mean, b.w);
        orow[idx] = o4;
    }
}

// ---------------------------------------------------------------------------
extern "C" void kernel_launch(void* const* d_in, const int* in_sizes, int n_in,
                              void* d_out, int out_size)
{
    const float* c   = (const float*)d_in[0];
    const float* h   = (const float*)d_in[1];
    const float* e   = (const float*)d_in[2];
    const float* s   = (const float*)d_in[3];
    const float* Wq  = (const float*)d_in[4];
    const float* bq  = (const float*)d_in[5];
    const float* Wk  = (const float*)d_in[6];
    /* bk = d_in[7] unused: constant across softmax axis, drops exactly */
    const float* Wv  = (const float*)d_in[8];
    const float* bv  = (const float*)d_in[9];
    const float* Wo  = (const float*)d_in[10];
    const float* bo  = (const float*)d_in[11];
    const float* la  = (const float*)d_in[12];
    const float* lb  = (const float*)d_in[13];
    float* out = (float*)d_out;

    void *pq, *pqt, *pw, *po, *py;
    cudaGetSymbolAddress(&pq,  g_q);
    cudaGetSymbolAddress(&pqt, g_qt);
    cudaGetSymbolAddress(&pw,  g_w);
    cudaGetSymbolAddress(&po,  g_o);
    cudaGetSymbolAddress(&py,  g_y);
    float* q  = (float*)pq;
    float* qt = (float*)pqt;
    float* w  = (float*)pw;
    float* o  = (float*)po;
    float* y  = (float*)py;

    // 1) qp = (h @ Wq^T + bq) * 0.125     [8192,512]
    gemm128x64<true><<<dim3(DIM / 64, NB / 128, 1), 256>>>(
        h, DIM, 0, Wq, DIM, 0, bq, 0, q, DIM, 0, DIM, 0.125f);

    // 2) qt[n,h,:] = qp_h[n,:64] @ Wk_h[64,512]   (batched over 8 heads)
    gemm128x64<false><<<dim3(DIM / 64, NB / 128, HEADS), 256>>>(
        q, DIM, 64, Wk, DIM, 64 * DIM, (const float*)0, 0,
        qt, HEADS * DIM, DIM, 64, 1.0f);

    // 3) attention core: scores -> softmax -> w[n,h,:]
    attn_core<<<NB, 256>>>(qt, c, h, e, s, w);

    // 4) o[n, h*64:(h+1)*64] = w[n,h,:] @ Wv_h^T + bv_h   (batched over heads)
    gemm128x64<true><<<dim3(1, NB / 128, HEADS), 256>>>(
        w, HEADS * DIM, DIM, Wv, DIM, 64 * DIM, bv, 64,
        o, DIM, 64, DIM, 1.0f);

    // 5) y = o @ Wo^T + bo
    gemm128x64<true><<<dim3(DIM / 64, NB / 128, 1), 256>>>(
        o, DIM, 0, Wo, DIM, 0, bo, 0, y, DIM, 0, DIM, 1.0f);

    // 6) out = LN(relu(y))
    relu_ln<<<NB / 8, 256>>>(y, la, lb, out);
}

// round 10
// speedup vs baseline: 1.0362x; 1.0362x over previous
#include <cuda_runtime.h>
#include <math.h>

// ---------------------------------------------------------------------------
// TransformerCell: out = LN(relu(MHA(q=h, kv=concat(c,h,e,s), 8 heads)))
// Factorized exact algebra:
//   qp   = (h @ Wq^T + bq) / 8                      [N,512]
//   qt_h = qp_h @ Wk_h                              [N,8,512]  (q.bk const -> drops)
//   s_hj = qt_h . ctx_j ; attn = softmax_j          per (n,h), 35 ctx rows
//   w_h  = sum_j attn_j * ctx_j                     [N,8,512]
//   o_h  = w_h @ Wv_h^T + bv_h                      [N,512]   (sum attn = 1)
//   y    = o @ Wo^T + bo ; out = LN(relu(y))  (std ddof=1, eps added to std)
// ---------------------------------------------------------------------------

#define NB    8192
#define DIM   512
#define HEADS 8
#define KCTX  35

__device__ __align__(16) float g_q [NB * DIM];          // 16 MB
__device__ __align__(16) float g_qt[NB * HEADS * DIM];  // 128 MB
__device__ __align__(16) float g_w [NB * HEADS * DIM];  // 128 MB
__device__ __align__(16) float g_o [NB * DIM];          // 16 MB
__device__ __align__(16) float g_y [NB * DIM];          // 16 MB

// ---------------------------------------------------------------------------
// fp32 GEMM, 256 threads, 8x8 register tile, BK=16, ping-pong smem (1 bar/tile).
// Configs: (BM,BN) = (128,128) or (256,64).
// BT=true : C[m][n] = (sum_k A[m][k]*B[n][k] + bias[n]) * alpha   (B is NxK)
// BT=false: C[m][n] = (sum_k A[m][k]*B[k][n] + bias[n]) * alpha   (B is KxN)
// blockIdx.z selects a batch (head) via element offsets {a,b,c,bias}Batch.
// All dims are exact multiples of the tiles for this problem; no edge guards.
// ---------------------------------------------------------------------------
template <bool BT, int BM, int BN>
__global__ void __launch_bounds__(256)
gemmTile(const float* __restrict__ A, int lda, int aBatch,
         const float* __restrict__ B, int ldb, int bBatch,
         const float* __restrict__ bias, int biasBatch,
         float* __restrict__ C, int ldc, int cBatch,
         int K, float alpha)
{
    __shared__ float As[2][16][BM];
    __shared__ float Bs[2][16][BN];

    const int tid = threadIdx.x;
    const int bm  = blockIdx.y * BM;
    const int bn  = blockIdx.x * BN;

    A += (long)blockIdx.z * aBatch + (long)bm * lda;
    B += (long)blockIdx.z * bBatch;
    C += (long)blockIdx.z * cBatch;
    const float* bptr = bias ? (bias + (long)blockIdx.z * biasBatch) : (const float*)0;

    // thread tile coordinates
    constexpr int TXN = BN / 8;              // threads along n
    const int tx = tid % TXN;                // 0..TXN-1
    const int ty = tid / TXN;                // 0..(256/TXN)-1
    const int rowBase = ty * 8;
    const int colBase = tx * 8;

    // A loader
    constexpr int A_VEC = (BM == 128) ? 2 : 4;         // float4 per thread
    const int aRow = (BM == 128) ? (tid >> 1) : tid;
    const int aKb  = (BM == 128) ? ((tid & 1) * 8) : 0;
    // B loader
    constexpr int B_VEC = BT ? (BN == 128 ? 2 : 1) : 2;
    const int bNr = BT ? ((BN == 128) ? (tid >> 1) : (tid >> 2)) : 0;
    const int bKb = BT ? ((BN == 128) ? ((tid & 1) * 8) : ((tid & 3) * 4)) : 0;
    const int bKr = BT ? 0 : (tid >> 4);               // !BT: k row
    const int bNb = BT ? 0 : ((tid & 15) * 8);         // !BT: n base

    float aRf[A_VEC * 4];
    float bRf[B_VEC * 4];

    float acc[8][8];
#pragma unroll
    for (int i = 0; i < 8; i++)
#pragma unroll
        for (int j = 0; j < 8; j++) acc[i][j] = 0.f;

    const int nT = K >> 4;

#define LOAD_TILE(k0)                                                          \
    {                                                                          \
        const float* ab = A + (long)aRow * lda + (k0) + aKb;                   \
        _Pragma("unroll")                                                      \
        for (int m = 0; m < A_VEC; m++)                                        \
            *(float4*)&aRf[4 * m] = *(const float4*)(ab + 4 * m);              \
        if (BT) {                                                              \
            const float* bb = B + (long)(bn + bNr) * ldb + (k0) + bKb;         \
            _Pragma("unroll")                                                  \
            for (int m = 0; m < B_VEC; m++)                                    \
                *(float4*)&bRf[4 * m] = *(const float4*)(bb + 4 * m);          \
        } else {                                                               \
            const float* bb = B + (long)((k0) + bKr) * ldb + bn + bNb;         \
            _Pragma("unroll")                                                  \
            for (int m = 0; m < B_VEC; m++)                                    \
                *(float4*)&bRf[4 * m] = *(const float4*)(bb + 4 * m);          \
        }                                                                      \
    }

#define STORE_TILE(buf)                                                        \
    {                                                                          \
        _Pragma("unroll")                                                      \
        for (int i = 0; i < A_VEC * 4; i++) As[buf][aKb + i][aRow] = aRf[i];   \
        if (BT) {                                                              \
            _Pragma("unroll")                                                  \
            for (int i = 0; i < B_VEC * 4; i++)                                \
                Bs[buf][bKb + i][bNr] = bRf[i];                                \
        } else {                                                               \
            *(float4*)&Bs[buf][bKr][bNb]     = *(float4*)&bRf[0];              \
            *(float4*)&Bs[buf][bKr][bNb + 4] = *(float4*)&bRf[4];              \
        }                                                                      \
    }

    LOAD_TILE(0);
    STORE_TILE(0);
    __syncthreads();

    for (int t = 0; t < nT; t++) {
        const int cur = t & 1;
        if (t + 1 < nT) LOAD_TILE((t + 1) * 16);

#pragma unroll
        for (int k = 0; k < 16; k++) {
            float a[8], b[8];
            *(float4*)&a[0] = *(const float4*)&As[cur][k][rowBase];
            *(float4*)&a[4] = *(const float4*)&As[cur][k][rowBase + 4];
            *(float4*)&b[0] = *(const float4*)&Bs[cur][k][colBase];
            *(float4*)&b[4] = *(const float4*)&Bs[cur][k][colBase + 4];
#pragma unroll
            for (int i = 0; i < 8; i++)
#pragma unroll
                for (int j = 0; j < 8; j++)
                    acc[i][j] = fmaf(a[i], b[j], acc[i][j]);
        }

        if (t + 1 < nT) {
            STORE_TILE(!cur);
            __syncthreads();
        }
    }
#undef LOAD_TILE
#undef STORE_TILE

    float bb[8] = {0.f, 0.f, 0.f, 0.f, 0.f, 0.f, 0.f, 0.f};
    if (bptr) {
#pragma unroll
        for (int j = 0; j < 8; j++) bb[j] = bptr[bn + colBase + j];
    }
#pragma unroll
    for (int i = 0; i < 8; i++) {
        float4 o0, o1;
        o0.x = (acc[i][0] + bb[0]) * alpha;
        o0.y = (acc[i][1] + bb[1]) * alpha;
        o0.z = (acc[i][2] + bb[2]) * alpha;
        o0.w = (acc[i][3] + bb[3]) * alpha;
        o1.x = (acc[i][4] + bb[4]) * alpha;
        o1.y = (acc[i][5] + bb[5]) * alpha;
        o1.z = (acc[i][6] + bb[6]) * alpha;
        o1.w = (acc[i][7] + bb[7]) * alpha;
        float* crow = C + (long)(bm + rowBase + i) * ldc + bn + colBase;
        *(float4*)crow       = o0;
        *(float4*)(crow + 4) = o1;
    }
}

// ---------------------------------------------------------------------------
// Attention core: one CTA per batch n, 256 threads = 8 warps.
// ctx (35x512 fp32 = 70KB) staged ONCE into dynamic smem; phases B and C read
// LDS only. qt rows stay in registers.
//  Phase B: warp (hp,jg) -> heads {2hp,2hp+1}, j-half
//  Softmax: warp h -> head h (35 scores across lanes)
//  Phase C: warp (hp,dh) -> heads {2hp,2hp+1}, 256-d half
// ---------------------------------------------------------------------------
__global__ void __launch_bounds__(256)
attn_core(const float* __restrict__ qt, const float* __restrict__ cc,
          const float* __restrict__ hv, const float* __restrict__ ev,
          const float* __restrict__ sv, float* __restrict__ wout)
{
    extern __shared__ float smbuf[];
    float* ctx   = smbuf;                    // [35][512]
    float* sc    = smbuf + KCTX * DIM;       // [8][35]
    float* attnw = sc + HEADS * KCTX;        // [8][35]

    const int n    = blockIdx.x;
    const int tid  = threadIdx.x;
    const int lane = tid & 31;
    const int warp = tid >> 5;

    // stage ctx: rows 0..31 from c[n] (contiguous 64KB), rows 32..34 = h,e,s
    {
        const float4* c4 = (const float4*)(cc + (long)n * 32 * DIM);
        float4* d4 = (float4*)ctx;
#pragma unroll 4
        for (int i = tid; i < 32 * DIM / 4; i += 256) d4[i] = c4[i];

        for (int i = tid; i < 3 * DIM / 4; i += 256) {
            const int r = i >> 7;            // 0..2
            const int v = i & 127;
            const float* src = (r == 0) ? hv : (r == 1) ? ev : sv;
            ((float4*)(ctx + (32 + r) * DIM))[v] =
                ((const float4*)(src + (long)n * DIM))[v];
        }
    }
    __syncthreads();

    const int hp = warp >> 1;
    const int h0 = hp * 2, h1 = h0 + 1;

    // ---- Phase B: scores ---------------------------------------------------
    {
        const float4* qa = (const float4*)(qt + (long)n * (HEADS * DIM) + h0 * DIM);
        const float4* qb = (const float4*)(qt + (long)n * (HEADS * DIM) + h1 * DIM);
        float4 ra[4], rb[4];
#pragma unroll
        for (int i = 0; i < 4; i++) { ra[i] = qa[lane + 32 * i]; rb[i] = qb[lane + 32 * i]; }

        const int jg = warp & 1;
        const int jb = jg ? 18 : 0;
        const int je = jg ? KCTX : 18;
        for (int j = jb; j < je; j++) {
            const float4* xp = (const float4*)(ctx + j * DIM);
            float p0 = 0.f, p1 = 0.f;
#pragma unroll
            for (int i = 0; i < 4; i++) {
                float4 x = xp[lane + 32 * i];
                p0 = fmaf(ra[i].x, x.x, p0); p0 = fmaf(ra[i].y, x.y, p0);
                p0 = fmaf(ra[i].z, x.z, p0); p0 = fmaf(ra[i].w, x.w, p0);
                p1 = fmaf(rb[i].x, x.x, p1); p1 = fmaf(rb[i].y, x.y, p1);
                p1 = fmaf(rb[i].z, x.z, p1); p1 = fmaf(rb[i].w, x.w, p1);
            }
#pragma unroll
            for (int o = 16; o; o >>= 1) {
                p0 += __shfl_xor_sync(0xffffffffu, p0, o);
                p1 += __shfl_xor_sync(0xffffffffu, p1, o);
            }
            if (lane == 0) { sc[h0 * KCTX + j] = p0; sc[h1 * KCTX + j] = p1; }
        }
    }
    __syncthreads();

    // ---- Softmax (warp = head) ----------------------------------------------
    {
        const int hh = warp;
        float s1 = sc[hh * KCTX + lane];
        float s2 = (lane < 3) ? sc[hh * KCTX + 32 + lane] : -3.0e38f;
        float m = fmaxf(s1, s2);
#pragma unroll
        for (int o = 16; o; o >>= 1)
            m = fmaxf(m, __shfl_xor_sync(0xffffffffu, m, o));
        float e1 = expf(s1 - m);
        float e2 = (lane < 3) ? expf(s2 - m) : 0.f;
        float sum = e1 + e2;
#pragma unroll
        for (int o = 16; o; o >>= 1)
            sum += __shfl_xor_sync(0xffffffffu, sum, o);
        float inv = 1.f / sum;
        attnw[hh * KCTX + lane] = e1 * inv;
        if (lane < 3) attnw[hh * KCTX + 32 + lane] = e2 * inv;
    }
    __syncthreads();

    // ---- Phase C: w = attn @ ctx --------------------------------------------
    {
        const int dh    = warp & 1;
        const int dbase = dh * 256;            // floats
        float4 acc[2][2];
#pragma unroll
        for (int hI = 0; hI < 2; hI++)
#pragma unroll
            for (int i = 0; i < 2; i++)
                acc[hI][i] = make_float4(0.f, 0.f, 0.f, 0.f);

        for (int j = 0; j < KCTX; j++) {
            const float4* xp = (const float4*)(ctx + j * DIM + dbase);
            float a0 = attnw[h0 * KCTX + j];
            float a1 = attnw[h1 * KCTX + j];
#pragma unroll
            for (int i = 0; i < 2; i++) {
                float4 x = xp[lane + 32 * i];
                acc[0][i].x = fmaf(a0, x.x, acc[0][i].x);
                acc[0][i].y = fmaf(a0, x.y, acc[0][i].y);
                acc[0][i].z = fmaf(a0, x.z, acc[0][i].z);
                acc[0][i].w = fmaf(a0, x.w, acc[0][i].w);
                acc[1][i].x = fmaf(a1, x.x, acc[1][i].x);
                acc[1][i].y = fmaf(a1, x.y, acc[1][i].y);
                acc[1][i].z = fmaf(a1, x.z, acc[1][i].z);
                acc[1][i].w = fmaf(a1, x.w, acc[1][i].w);
            }
        }
        float4* w0 = (float4*)(wout + (long)n * (HEADS * DIM) + h0 * DIM + dbase);
        float4* w1 = (float4*)(wout + (long)n * (HEADS * DIM) + h1 * DIM + dbase);
#pragma unroll
        for (int i = 0; i < 2; i++) {
            w0[lane + 32 * i] = acc[0][i];
            w1[lane + 32 * i] = acc[1][i];
        }
    }
}

// ---------------------------------------------------------------------------
// relu + LayerNorm (ddof=1, eps added to STD). One warp per row.
// ---------------------------------------------------------------------------
__global__ void __launch_bounds__(256)
relu_ln(const float* __restrict__ y, const float* __restrict__ ln_a,
        const float* __restrict__ ln_b, float* __restrict__ out)
{
    const int lane = threadIdx.x & 31;
    const int warp = threadIdx.x >> 5;
    const int row  = blockIdx.x * 8 + warp;

    const float4* xr = (const float4*)(y + (long)row * DIM);
    float4 v[4];
    float sum = 0.f;
#pragma unroll
    for (int i = 0; i < 4; i++) {
        float4 x = xr[lane + 32 * i];
        x.x = fmaxf(x.x, 0.f); x.y = fmaxf(x.y, 0.f);
        x.z = fmaxf(x.z, 0.f); x.w = fmaxf(x.w, 0.f);
        v[i] = x;
        sum += x.x + x.y + x.z + x.w;
    }
#pragma unroll
    for (int o = 16; o; o >>= 1) sum += __shfl_xor_sync(0xffffffffu, sum, o);
    const float mean = sum * (1.f / (float)DIM);

    float ssq = 0.f;
#pragma unroll
    for (int i = 0; i < 4; i++) {
        float dx;
        dx = v[i].x - mean; ssq = fmaf(dx, dx, ssq);
        dx = v[i].y - mean; ssq = fmaf(dx, dx, ssq);
        dx = v[i].z - mean; ssq = fmaf(dx, dx, ssq);
        dx = v[i].w - mean; ssq = fmaf(dx, dx, ssq);
    }
#pragma unroll
    for (int o = 16; o; o >>= 1) ssq += __shfl_xor_sync(0xffffffffu, ssq, o);
    const float stddev = sqrtf(ssq * (1.f / (float)(DIM - 1)));
    const float inv = 1.f / (stddev + 1e-6f);

    float4* orow = (float4*)(out + (long)row * DIM);
    const float4* a4 = (const float4*)ln_a;
    const float4* b4 = (const float4*)ln_b;
#pragma unroll
    for (int i = 0; i < 4; i++) {
        const int idx = lane + 32 * i;
        float4 a = a4[idx], b = b4[idx], o4;
        o4.x = fmaf(a.x * inv, v[i].x - mean, b.x);
        o4.y = fmaf(a.y * inv, v[i].y - mean, b.y);
        o4.z = fmaf(a.z * inv, v[i].z - mean, b.z);
        o4.w = fmaf(a.w * inv, v[i].w - mean, b.w);
        orow[idx] = o4;
    }
}

// ---------------------------------------------------------------------------
extern "C" void kernel_launch(void* const* d_in, const int* in_sizes, int n_in,
                              void* d_out, int out_size)
{
    const float* c   = (const float*)d_in[0];
    const float* h   = (const float*)d_in[1];
    const float* e   = (const float*)d_in[2];
    const float* s   = (const float*)d_in[3];
    const float* Wq  = (const float*)d_in[4];
    const float* bq  = (const float*)d_in[5];
    const float* Wk  = (const float*)d_in[6];
    /* bk = d_in[7] unused: constant across softmax axis, drops exactly */
    const float* Wv  = (const float*)d_in[8];
    const float* bv  = (const float*)d_in[9];
    const float* Wo  = (const float*)d_in[10];
    const float* bo  = (const float*)d_in[11];
    const float* la  = (const float*)d_in[12];
    const float* lb  = (const float*)d_in[13];
    float* out = (float*)d_out;

    void *pq, *pqt, *pw, *po, *py;
    cudaGetSymbolAddress(&pq,  g_q);
    cudaGetSymbolAddress(&pqt, g_qt);
    cudaGetSymbolAddress(&pw,  g_w);
    cudaGetSymbolAddress(&po,  g_o);
    cudaGetSymbolAddress(&py,  g_y);
    float* q  = (float*)pq;
    float* qt = (float*)pqt;
    float* w  = (float*)pw;
    float* o  = (float*)po;
    float* y  = (float*)py;

    const int ATTN_SMEM = (KCTX * DIM + 2 * HEADS * KCTX) * (int)sizeof(float);
    cudaFuncSetAttribute(attn_core, cudaFuncAttributeMaxDynamicSharedMemorySize,
                         ATTN_SMEM);

    // 1) qp = (h @ Wq^T + bq) * 0.125     [8192,512]
    gemmTile<true, 128, 128><<<dim3(DIM / 128, NB / 128, 1), 256>>>(
        h, DIM, 0, Wq, DIM, 0, bq, 0, q, DIM, 0, DIM, 0.125f);

    // 2) qt[n,h,:] = qp_h[n,:64] @ Wk_h[64,512]   (batched over 8 heads)
    gemmTile<false, 128, 128><<<dim3(DIM / 128, NB / 128, HEADS), 256>>>(
        q, DIM, 64, Wk, DIM, 64 * DIM, (const float*)0, 0,
        qt, HEADS * DIM, DIM, 64, 1.0f);

    // 3) attention core: scores -> softmax -> w[n,h,:]
    attn_core<<<NB, 256, ATTN_SMEM>>>(qt, c, h, e, s, w);

    // 4) o[n, h*64:(h+1)*64] = w[n,h,:] @ Wv_h^T + bv_h   (batched over heads)
    gemmTile<true, 256, 64><<<dim3(1, NB / 256, HEADS), 256>>>(
        w, HEADS * DIM, DIM, Wv, DIM, 64 * DIM, bv, 64,
        o, DIM, 64, DIM, 1.0f);

    // 5) y = o @ Wo^T + bo
    gemmTile<true, 128, 128><<<dim3(DIM / 128, NB / 128, 1), 256>>>(
        o, DIM, 0, Wo, DIM, 0, bo, 0, y, DIM, 0, DIM, 1.0f);

    // 6) out = LN(relu(y))
    relu_ln<<<NB / 8, 256>>>(y, la, lb, out);
}

// round 11
// speedup vs baseline: 1.0806x; 1.0429x over previous
#include <cuda_runtime.h>
#include <math.h>

// ---------------------------------------------------------------------------
// TransformerCell: out = LN(relu(MHA(q=h, kv=concat(c,h,e,s), 8 heads)))
// Factorized exact algebra:
//   qp   = (h @ Wq^T + bq) / 8                      [N,512]
//   qt_h = qp_h @ Wk_h                              [N,8,512]  (q.bk const -> drops)
//   s_hj = qt_h . ctx_j ; attn = softmax_j          per (n,h), 35 ctx rows
//   w_h  = sum_j attn_j * ctx_j                     [N,8,512]
//   o_h  = w_h @ Wv_h^T + bv_h                      [N,512]   (sum attn = 1)
//   y    = o @ Wo^T + bo ; out = LN(relu(y))  (std ddof=1, eps added to std)
// All fp32; hot loops use packed fma.rn.f32x2 (bit-identical to scalar FFMA).
// ---------------------------------------------------------------------------

#define NB    8192
#define DIM   512
#define HEADS 8
#define KCTX  35

typedef unsigned long long u64;

__device__ __align__(16) float g_q [NB * DIM];          // 16 MB
__device__ __align__(16) float g_qt[NB * HEADS * DIM];  // 128 MB
__device__ __align__(16) float g_w [NB * HEADS * DIM];  // 128 MB
__device__ __align__(16) float g_o [NB * DIM];          // 16 MB
__device__ __align__(16) float g_y [NB * DIM];          // 16 MB

__device__ __forceinline__ u64 pack2(float x, float y) {
    u64 r;
    asm("mov.b64 %0, {%1, %2};" : "=l"(r) : "f"(x), "f"(y));
    return r;
}
__device__ __forceinline__ void fma2(u64& d, u64 a, u64 b) {
    asm("fma.rn.f32x2 %0, %1, %2, %0;" : "+l"(d) : "l"(a), "l"(b));
}
__device__ __forceinline__ float2 unpack2(u64 v) {
    float2 f;
    asm("mov.b64 {%0, %1}, %2;" : "=f"(f.x), "=f"(f.y) : "l"(v));
    return f;
}

// ---------------------------------------------------------------------------
// fp32 GEMM, 256 threads, 8x8 register tile, BK=16, ping-pong smem,
// packed f32x2 inner product (32 FFMA2 per k-step per thread).
// BT=true : C[m][n] = (sum_k A[m][k]*B[n][k] + bias[n]) * alpha   (B is NxK)
// BT=false: C[m][n] = (sum_k A[m][k]*B[k][n] + bias[n]) * alpha   (B is KxN)
// blockIdx.z selects a batch (head) via element offsets {a,b,c,bias}Batch.
// All dims are exact multiples of the tiles for this problem; no edge guards.
// ---------------------------------------------------------------------------
template <bool BT, int BM, int BN>
__global__ void __launch_bounds__(256)
gemmTile(const float* __restrict__ A, int lda, int aBatch,
         const float* __restrict__ B, int ldb, int bBatch,
         const float* __restrict__ bias, int biasBatch,
         float* __restrict__ C, int ldc, int cBatch,
         int K, float alpha)
{
    __shared__ __align__(16) float As[2][16][BM];
    __shared__ __align__(16) float Bs[2][16][BN];

    const int tid = threadIdx.x;
    const int bm  = blockIdx.y * BM;
    const int bn  = blockIdx.x * BN;

    A += (long)blockIdx.z * aBatch + (long)bm * lda;
    B += (long)blockIdx.z * bBatch;
    C += (long)blockIdx.z * cBatch;
    const float* bptr = bias ? (bias + (long)blockIdx.z * biasBatch) : (const float*)0;

    // thread tile coordinates
    constexpr int TXN = BN / 8;              // threads along n
    const int tx = tid % TXN;
    const int ty = tid / TXN;
    const int rowBase = ty * 8;
    const int colBase = tx * 8;

    // A loader
    constexpr int A_VEC = (BM == 128) ? 2 : 4;         // float4 per thread
    const int aRow = (BM == 128) ? (tid >> 1) : tid;
    const int aKb  = (BM == 128) ? ((tid & 1) * 8) : 0;
    // B loader
    constexpr int B_VEC = BT ? (BN == 128 ? 2 : 1) : 2;
    const int bNr = BT ? ((BN == 128) ? (tid >> 1) : (tid >> 2)) : 0;
    const int bKb = BT ? ((BN == 128) ? ((tid & 1) * 8) : ((tid & 3) * 4)) : 0;
    const int bKr = BT ? 0 : (tid >> 4);               // !BT: k row
    const int bNb = BT ? 0 : ((tid & 15) * 8);         // !BT: n base

    float aRf[A_VEC * 4];
    float bRf[B_VEC * 4];

    u64 acc2[8][4];
#pragma unroll
    for (int i = 0; i < 8; i++)
#pragma unroll
        for (int j = 0; j < 4; j++) acc2[i][j] = 0ull;   // two packed +0.0f

    const int nT = K >> 4;

#define LOAD_TILE(k0)                                                          \
    {                                                                          \
        const float* ab = A + (long)aRow * lda + (k0) + aKb;                   \
        _Pragma("unroll")                                                      \
        for (int m = 0; m < A_VEC; m++)                                        \
            *(float4*)&aRf[4 * m] = *(const float4*)(ab + 4 * m);              \
        if (BT) {                                                              \
            const float* bb = B + (long)(bn + bNr) * ldb + (k0) + bKb;         \
            _Pragma("unroll")                                                  \
            for (int m = 0; m < B_VEC; m++)                                    \
                *(float4*)&bRf[4 * m] = *(const float4*)(bb + 4 * m);          \
        } else {                                                               \
            const float* bb = B + (long)((k0) + bKr) * ldb + bn + bNb;         \
            _Pragma("unroll")                                                  \
            for (int m = 0; m < B_VEC; m++)                                    \
                *(float4*)&bRf[4 * m] = *(const float4*)(bb + 4 * m);          \
        }                                                                      \
    }

#define STORE_TILE(buf)                                                        \
    {                                                                          \
        _Pragma("unroll")                                                      \
        for (int i = 0; i < A_VEC * 4; i++) As[buf][aKb + i][aRow] = aRf[i];   \
        if (BT) {                                                              \
            _Pragma("unroll")                                                  \
            for (int i = 0; i < B_VEC * 4; i++)                                \
                Bs[buf][bKb + i][bNr] = bRf[i];                                \
        } else {                                                               \
            *(float4*)&Bs[buf][bKr][bNb]     = *(float4*)&bRf[0];              \
            *(float4*)&Bs[buf][bKr][bNb + 4] = *(float4*)&bRf[4];              \
        }                                                                      \
    }

    LOAD_TILE(0);
    STORE_TILE(0);
    __syncthreads();

    for (int t = 0; t < nT; t++) {
        const int cur = t & 1;
        if (t + 1 < nT) LOAD_TILE((t + 1) * 16);

#pragma unroll
        for (int k = 0; k < 16; k++) {
            float a[8];
            *(float4*)&a[0] = *(const float4*)&As[cur][k][rowBase];
            *(float4*)&a[4] = *(const float4*)&As[cur][k][rowBase + 4];
            ulonglong2 bA = *(const ulonglong2*)&Bs[cur][k][colBase];
            ulonglong2 bB = *(const ulonglong2*)&Bs[cur][k][colBase + 4];
            u64 b2[4] = {bA.x, bA.y, bB.x, bB.y};
#pragma unroll
            for (int i = 0; i < 8; i++) {
                u64 ad = pack2(a[i], a[i]);
#pragma unroll
                for (int j = 0; j < 4; j++) fma2(acc2[i][j], ad, b2[j]);
            }
        }

        if (t + 1 < nT) {
            STORE_TILE(!cur);
            __syncthreads();
        }
    }
#undef LOAD_TILE
#undef STORE_TILE

    float bb[8] = {0.f, 0.f, 0.f, 0.f, 0.f, 0.f, 0.f, 0.f};
    if (bptr) {
#pragma unroll
        for (int j = 0; j < 8; j++) bb[j] = bptr[bn + colBase + j];
    }
#pragma unroll
    for (int i = 0; i < 8; i++) {
        float2 p0 = unpack2(acc2[i][0]);
        float2 p1 = unpack2(acc2[i][1]);
        float2 p2 = unpack2(acc2[i][2]);
        float2 p3 = unpack2(acc2[i][3]);
        float4 o0, o1;
        o0.x = (p0.x + bb[0]) * alpha;
        o0.y = (p0.y + bb[1]) * alpha;
        o0.z = (p1.x + bb[2]) * alpha;
        o0.w = (p1.y + bb[3]) * alpha;
        o1.x = (p2.x + bb[4]) * alpha;
        o1.y = (p2.y + bb[5]) * alpha;
        o1.z = (p3.x + bb[6]) * alpha;
        o1.w = (p3.y + bb[7]) * alpha;
        float* crow = C + (long)(bm + rowBase + i) * ldc + bn + colBase;
        *(float4*)crow       = o0;
        *(float4*)(crow + 4) = o1;
    }
}

// ---------------------------------------------------------------------------
// Attention core: one CTA per batch n, 256 threads = 8 warps.
// ctx (35x512 fp32 = 70KB) staged ONCE into dynamic smem; packed f32x2 math.
//  Phase B: warp (hp,jg) -> heads {2hp,2hp+1}, j-half
//  Softmax: warp h -> head h (35 scores across lanes)
//  Phase C: warp (hp,dh) -> heads {2hp,2hp+1}, 256-d half
// ---------------------------------------------------------------------------
__global__ void __launch_bounds__(256)
attn_core(const float* __restrict__ qt, const float* __restrict__ cc,
          const float* __restrict__ hv, const float* __restrict__ ev,
          const float* __restrict__ sv, float* __restrict__ wout)
{
    extern __shared__ __align__(16) float smbuf[];
    float* ctx   = smbuf;                    // [35][512]
    float* sc    = smbuf + KCTX * DIM;       // [8][35]
    float* attnw = sc + HEADS * KCTX;        // [8][35]

    const int n    = blockIdx.x;
    const int tid  = threadIdx.x;
    const int lane = tid & 31;
    const int warp = tid >> 5;

    // stage ctx: rows 0..31 from c[n] (contiguous 64KB), rows 32..34 = h,e,s
    {
        const float4* c4 = (const float4*)(cc + (long)n * 32 * DIM);
        float4* d4 = (float4*)ctx;
#pragma unroll 4
        for (int i = tid; i < 32 * DIM / 4; i += 256) d4[i] = c4[i];

        for (int i = tid; i < 3 * DIM / 4; i += 256) {
            const int r = i >> 7;            // 0..2
            const int v = i & 127;
            const float* src = (r == 0) ? hv : (r == 1) ? ev : sv;
            ((float4*)(ctx + (32 + r) * DIM))[v] =
                ((const float4*)(src + (long)n * DIM))[v];
        }
    }
    __syncthreads();

    const int hp = warp >> 1;
    const int h0 = hp * 2, h1 = h0 + 1;

    // ---- Phase B: scores ---------------------------------------------------
    {
        const float4* qa = (const float4*)(qt + (long)n * (HEADS * DIM) + h0 * DIM);
        const float4* qb = (const float4*)(qt + (long)n * (HEADS * DIM) + h1 * DIM);
        u64 qa2[8], qb2[8];
#pragma unroll
        for (int i = 0; i < 4; i++) {
            float4 ra = qa[lane + 32 * i];
            float4 rb = qb[lane + 32 * i];
            qa2[2 * i]     = pack2(ra.x, ra.y);
            qa2[2 * i + 1] = pack2(ra.z, ra.w);
            qb2[2 * i]     = pack2(rb.x, rb.y);
            qb2[2 * i + 1] = pack2(rb.z, rb.w);
        }

        const int jg = warp & 1;
        const int jb = jg ? 18 : 0;
        const int je = jg ? KCTX : 18;
        for (int j = jb; j < je; j++) {
            const ulonglong2* xp = (const ulonglong2*)(ctx + j * DIM);
            u64 p0 = 0ull, p1 = 0ull;
#pragma unroll
            for (int i = 0; i < 4; i++) {
                ulonglong2 x = xp[lane + 32 * i];
                fma2(p0, qa2[2 * i],     x.x);
                fma2(p0, qa2[2 * i + 1], x.y);
                fma2(p1, qb2[2 * i],     x.x);
                fma2(p1, qb2[2 * i + 1], x.y);
            }
            float2 f0 = unpack2(p0);
            float2 f1 = unpack2(p1);
            float s0 = f0.x + f0.y;
            float s1 = f1.x + f1.y;
#pragma unroll
            for (int o = 16; o; o >>= 1) {
                s0 += __shfl_xor_sync(0xffffffffu, s0, o);
                s1 += __shfl_xor_sync(0xffffffffu, s1, o);
            }
            if (lane == 0) { sc[h0 * KCTX + j] = s0; sc[h1 * KCTX + j] = s1; }
        }
    }
    __syncthreads();

    // ---- Softmax (warp = head) ----------------------------------------------
    {
        const int hh = warp;
        float s1 = sc[hh * KCTX + lane];
        float s2 = (lane < 3) ? sc[hh * KCTX + 32 + lane] : -3.0e38f;
        float m = fmaxf(s1, s2);
#pragma unroll
        for (int o = 16; o; o >>= 1)
            m = fmaxf(m, __shfl_xor_sync(0xffffffffu, m, o));
        float e1 = expf(s1 - m);
        float e2 = (lane < 3) ? expf(s2 - m) : 0.f;
        float sum = e1 + e2;
#pragma unroll
        for (int o = 16; o; o >>= 1)
            sum += __shfl_xor_sync(0xffffffffu, sum, o);
        float inv = 1.f / sum;
        attnw[hh * KCTX + lane] = e1 * inv;
        if (lane < 3) attnw[hh * KCTX + 32 + lane] = e2 * inv;
    }
    __syncthreads();

    // ---- Phase C: w = attn @ ctx --------------------------------------------
    {
        const int dh    = warp & 1;
        const int dbase = dh * 256;            // floats
        u64 acc2[2][4];
#pragma unroll
        for (int hI = 0; hI < 2; hI++)
#pragma unroll
            for (int p = 0; p < 4; p++) acc2[hI][p] = 0ull;

        for (int j = 0; j < KCTX; j++) {
            const ulonglong2* xp = (const ulonglong2*)(ctx + j * DIM + dbase);
            u64 a0d = pack2(attnw[h0 * KCTX + j], attnw[h0 * KCTX + j]);
            u64 a1d = pack2(attnw[h1 * KCTX + j], attnw[h1 * KCTX + j]);
#pragma unroll
            for (int i = 0; i < 2; i++) {
                ulonglong2 x = xp[lane + 32 * i];
                fma2(acc2[0][2 * i],     a0d, x.x);
                fma2(acc2[0][2 * i + 1], a0d, x.y);
                fma2(acc2[1][2 * i],     a1d, x.x);
                fma2(acc2[1][2 * i + 1], a1d, x.y);
            }
        }
        float4* w0 = (float4*)(wout + (long)n * (HEADS * DIM) + h0 * DIM + dbase);
        float4* w1 = (float4*)(wout + (long)n * (HEADS * DIM) + h1 * DIM + dbase);
#pragma unroll
        for (int i = 0; i < 2; i++) {
            float2 a = unpack2(acc2[0][2 * i]);
            float2 b = unpack2(acc2[0][2 * i + 1]);
            w0[lane + 32 * i] = make_float4(a.x, a.y, b.x, b.y);
            float2 c0 = unpack2(acc2[1][2 * i]);
            float2 d0 = unpack2(acc2[1][2 * i + 1]);
            w1[lane + 32 * i] = make_float4(c0.x, c0.y, d0.x, d0.y);
        }
    }
}

// ---------------------------------------------------------------------------
// relu + LayerNorm (ddof=1, eps added to STD). One warp per row.
// ---------------------------------------------------------------------------
__global__ void __launch_bounds__(256)
relu_ln(const float* __restrict__ y, const float* __restrict__ ln_a,
        const float* __restrict__ ln_b, float* __restrict__ out)
{
    const int lane = threadIdx.x & 31;
    const int warp = threadIdx.x >> 5;
    const int row  = blockIdx.x * 8 + warp;

    const float4* xr = (const float4*)(y + (long)row * DIM);
    float4 v[4];
    float sum = 0.f;
#pragma unroll
    for (int i = 0; i < 4; i++) {
        float4 x = xr[lane + 32 * i];
        x.x = fmaxf(x.x, 0.f); x.y = fmaxf(x.y, 0.f);
        x.z = fmaxf(x.z, 0.f); x.w = fmaxf(x.w, 0.f);
        v[i] = x;
        sum += x.x + x.y + x.z + x.w;
    }
#pragma unroll
    for (int o = 16; o; o >>= 1) sum += __shfl_xor_sync(0xffffffffu, sum, o);
    const float mean = sum * (1.f / (float)DIM);

    float ssq = 0.f;
#pragma unroll
    for (int i = 0; i < 4; i++) {
        float dx;
        dx = v[i].x - mean; ssq = fmaf(dx, dx, ssq);
        dx = v[i].y - mean; ssq = fmaf(dx, dx, ssq);
        dx = v[i].z - mean; ssq = fmaf(dx, dx, ssq);
        dx = v[i].w - mean; ssq = fmaf(dx, dx, ssq);
    }
#pragma unroll
    for (int o = 16; o; o >>= 1) ssq += __shfl_xor_sync(0xffffffffu, ssq, o);
    const float stddev = sqrtf(ssq * (1.f / (float)(DIM - 1)));
    const float inv = 1.f / (stddev + 1e-6f);

    float4* orow = (float4*)(out + (long)row * DIM);
    const float4* a4 = (const float4*)ln_a;
    const float4* b4 = (const float4*)ln_b;
#pragma unroll
    for (int i = 0; i < 4; i++) {
        const int idx = lane + 32 * i;
        float4 a = a4[idx], b = b4[idx], o4;
        o4.x = fmaf(a.x * inv, v[i].x - mean, b.x);
        o4.y = fmaf(a.y * inv, v[i].y - mean, b.y);
        o4.z = fmaf(a.z * inv, v[i].z - mean, b.z);
        o4.w = fmaf(a.w * inv, v[i].w - mean, b.w);
        orow[idx] = o4;
    }
}

// ---------------------------------------------------------------------------
extern "C" void kernel_launch(void* const* d_in, const int* in_sizes, int n_in,
                              void* d_out, int out_size)
{
    const float* c   = (const float*)d_in[0];
    const float* h   = (const float*)d_in[1];
    const float* e   = (const float*)d_in[2];
    const float* s   = (const float*)d_in[3];
    const float* Wq  = (const float*)d_in[4];
    const float* bq  = (const float*)d_in[5];
    const float* Wk  = (const float*)d_in[6];
    /* bk = d_in[7] unused: constant across softmax axis, drops exactly */
    const float* Wv  = (const float*)d_in[8];
    const float* bv  = (const float*)d_in[9];
    const float* Wo  = (const float*)d_in[10];
    const float* bo  = (const float*)d_in[11];
    const float* la  = (const float*)d_in[12];
    const float* lb  = (const float*)d_in[13];
    float* out = (float*)d_out;

    void *pq, *pqt, *pw, *po, *py;
    cudaGetSymbolAddress(&pq,  g_q);
    cudaGetSymbolAddress(&pqt, g_qt);
    cudaGetSymbolAddress(&pw,  g_w);
    cudaGetSymbolAddress(&po,  g_o);
    cudaGetSymbolAddress(&py,  g_y);
    float* q  = (float*)pq;
    float* qt = (float*)pqt;
    float* w  = (float*)pw;
    float* o  = (float*)po;
    float* y  = (float*)py;

    const int ATTN_SMEM = (KCTX * DIM + 2 * HEADS * KCTX) * (int)sizeof(float);
    cudaFuncSetAttribute(attn_core, cudaFuncAttributeMaxDynamicSharedMemorySize,
                         ATTN_SMEM);

    // 1) qp = (h @ Wq^T + bq) * 0.125     [8192,512]
    gemmTile<true, 128, 128><<<dim3(DIM / 128, NB / 128, 1), 256>>>(
        h, DIM, 0, Wq, DIM, 0, bq, 0, q, DIM, 0, DIM, 0.125f);

    // 2) qt[n,h,:] = qp_h[n,:64] @ Wk_h[64,512]   (batched over 8 heads)
    gemmTile<false, 128, 128><<<dim3(DIM / 128, NB / 128, HEADS), 256>>>(
        q, DIM, 64, Wk, DIM, 64 * DIM, (const float*)0, 0,
        qt, HEADS * DIM, DIM, 64, 1.0f);

    // 3) attention core: scores -> softmax -> w[n,h,:]
    attn_core<<<NB, 256, ATTN_SMEM>>>(qt, c, h, e, s, w);

    // 4) o[n, h*64:(h+1)*64] = w[n,h,:] @ Wv_h^T + bv_h   (batched over heads)
    gemmTile<true, 256, 64><<<dim3(1, NB / 256, HEADS), 256>>>(
        w, HEADS * DIM, DIM, Wv, DIM, 64 * DIM, bv, 64,
        o, DIM, 64, DIM, 1.0f);

    // 5) y = o @ Wo^T + bo
    gemmTile<true, 128, 128><<<dim3(DIM / 128, NB / 128, 1), 256>>>(
        o, DIM, 0, Wo, DIM, 0, bo, 0, y, DIM, 0, DIM, 1.0f);

    // 6) out = LN(relu(y))
    relu_ln<<<NB / 8, 256>>>(y, la, lb, out);
}

// round 13
// speedup vs baseline: 1.3855x; 1.2822x over previous
#include <cuda_runtime.h>
#include <cuda_bf16.h>
#include <mma.h>
#include <math.h>

using namespace nvcuda;

// ---------------------------------------------------------------------------
// TransformerCell: out = LN(relu(MHA(q=h, kv=concat(c,h,e,s), 8 heads)))
// Factorized exact algebra; GEMMs on wmma bf16 (HMMA) with hi/lo split
// (3-product MMA, ~1e-5 rel err):
//   qp   = (h @ Wq^T + bq) / 8                  [N,512]   (tensor, split out)
//   qt_h = qp_h @ WkT_h^T                       [N,8,512] (tensor, fp32 out)
//   attn core (SIMT fp32)  -> w split bf16      [N,8,512]
//   o_h  = w_h @ Wv_h^T + bv_h                  [N,512]   (tensor, split out)
//   y    = o @ Wo^T + bo                        [N,512]   (tensor, fp32 out)
//   out = LN(relu(y))
// ---------------------------------------------------------------------------

#define NB    8192
#define DIM   512
#define HEADS 8
#define KCTX  35

typedef unsigned long long u64;
typedef unsigned int       u32;

// ---------------- scratch (device globals; no runtime allocation) ----------
__device__ __align__(16) __nv_bfloat16 g_h_hi [NB * DIM];
__device__ __align__(16) __nv_bfloat16 g_h_lo [NB * DIM];
__device__ __align__(16) __nv_bfloat16 g_wq_hi[DIM * DIM];
__device__ __align__(16) __nv_bfloat16 g_wq_lo[DIM * DIM];
__device__ __align__(16) __nv_bfloat16 g_wkT_hi[DIM * DIM];   // [h][512][64] K-major
__device__ __align__(16) __nv_bfloat16 g_wkT_lo[DIM * DIM];
__device__ __align__(16) __nv_bfloat16 g_wv_hi[DIM * DIM];
__device__ __align__(16) __nv_bfloat16 g_wv_lo[DIM * DIM];
__device__ __align__(16) __nv_bfloat16 g_wo_hi[DIM * DIM];
__device__ __align__(16) __nv_bfloat16 g_wo_lo[DIM * DIM];
__device__ __align__(16) __nv_bfloat16 g_qp_hi[NB * DIM];
__device__ __align__(16) __nv_bfloat16 g_qp_lo[NB * DIM];
__device__ __align__(16) float         g_qt  [NB * HEADS * DIM];   // 128 MB
__device__ __align__(16) __nv_bfloat16 g_w_hi[NB * HEADS * DIM];   // 64 MB
__device__ __align__(16) __nv_bfloat16 g_w_lo[NB * HEADS * DIM];   // 64 MB
__device__ __align__(16) __nv_bfloat16 g_o_hi[NB * DIM];
__device__ __align__(16) __nv_bfloat16 g_o_lo[NB * DIM];
__device__ __align__(16) float         g_y   [NB * DIM];

// split fp32 -> bf16 hi + bf16 lo (lo = rn(residual))
__device__ __forceinline__ void split1(float v, __nv_bfloat16& hi, __nv_bfloat16& lo) {
    hi = __float2bfloat16(v);
    lo = __float2bfloat16(v - __bfloat162float(hi));
}
__device__ __forceinline__ void split_store4(__nv_bfloat16* hp, __nv_bfloat16* lp, float4 f) {
    union { __nv_bfloat16 b[4]; uint2 u; } H, L;
    split1(f.x, H.b[0], L.b[0]);
    split1(f.y, H.b[1], L.b[1]);
    split1(f.z, H.b[2], L.b[2]);
    split1(f.w, H.b[3], L.b[3]);
    *(uint2*)hp = H.u;
    *(uint2*)lp = L.u;
}

// ---------------------------------------------------------------------------
// split conversion kernels
// ---------------------------------------------------------------------------
__global__ void __launch_bounds__(256)
splitF32(const float* __restrict__ x, __nv_bfloat16* __restrict__ hi,
         __nv_bfloat16* __restrict__ lo)
{
    const int i = blockIdx.x * 256 + threadIdx.x;   // float4 index
    float4 v = ((const float4*)x)[i];
    split_store4(hi + 4 * (long)i, lo + 4 * (long)i, v);
}

// WkT[h][n][k] = split(Wk[h*64+k][n]); flat t = h*32768 + n*64 + k
__global__ void __launch_bounds__(256)
splitWkT(const float* __restrict__ Wk, __nv_bfloat16* __restrict__ hi,
         __nv_bfloat16* __restrict__ lo)
{
    const int t = blockIdx.x * 256 + threadIdx.x;
    const int k = t & 63, n = (t >> 6) & 511, h = t >> 15;
    float v = Wk[(h * 64 + k) * DIM + n];
    __nv_bfloat16 a, b;
    split1(v, a, b);
    hi[t] = a; lo[t] = b;
}

// ---------------------------------------------------------------------------
// wmma bf16 GEMM with hi/lo split (3 products):
//   C[m, z*cz + bn + j] = (sum_k A[m,k]*B[n,k] + bias[n+...]) * alpha
// A split bf16 [*, lda], per-z offset az; B split bf16 [n, ldb], per-z bz.
// Block: 256 thr = 8 warps (4 m x 2 n). Tile M=128, N=BN, BK=32, single buffer.
// SMEM rows padded to ld=40 bf16 (80B, multiple of 16B for wmma).
// Epilogue: store_matrix_sync to smem C overlay, then bias/alpha/(split) out.
// ---------------------------------------------------------------------------
template <int BN, bool SPLIT_OUT>
__global__ void __launch_bounds__(256)
wmmaGemm(const __nv_bfloat16* __restrict__ aHi, const __nv_bfloat16* __restrict__ aLo,
         int lda, int az,
         const __nv_bfloat16* __restrict__ bHi, const __nv_bfloat16* __restrict__ bLo,
         int ldb, int bz,
         const float* __restrict__ bias, int biasz,
         float* __restrict__ cF,
         __nv_bfloat16* __restrict__ cHi, __nv_bfloat16* __restrict__ cLo,
         int ldc, long cz,
         int K, float alpha)
{
    extern __shared__ __align__(16) char smem[];
    constexpr int LDS   = 40;                         // padded bf16 ld
    constexpr int A_SZ  = 128 * LDS * 2;              // bytes per A matrix
    constexpr int B_SZ  = BN * LDS * 2;
    constexpr int OFF_BIAS = 0;
    constexpr int OFF_A_HI = 1024;
    constexpr int OFF_A_LO = OFF_A_HI + A_SZ;
    constexpr int OFF_B_HI = OFF_A_LO + A_SZ;
    constexpr int OFF_B_LO = OFF_B_HI + B_SZ;
    constexpr int OFF_C    = 1024;                    // overlays A/B post-mainloop
    constexpr int WN    = BN / 2;                     // warp tile n
    constexpr int NFRAG = WN / 16;

    const int tid  = threadIdx.x;
    const int wid  = tid >> 5;
    const int bm   = blockIdx.y * 128;
    const int bn   = blockIdx.x * BN;
    const int z    = blockIdx.z;
    const int wm   = (wid >> 1) * 32;                 // warp m offset in tile
    const int wn   = (wid & 1) * WN;                  // warp n offset in tile

    aHi += (long)z * az;  aLo += (long)z * az;
    bHi += (long)z * bz;  bLo += (long)z * bz;

    if (tid < BN) {
        float bvv = bias ? bias[(long)z * biasz + bn + tid] : 0.f;
        *(float*)(smem + OFF_BIAS + tid * 4) = bvv;
    }

    __nv_bfloat16* AsHi = (__nv_bfloat16*)(smem + OFF_A_HI);
    __nv_bfloat16* AsLo = (__nv_bfloat16*)(smem + OFF_A_LO);
    __nv_bfloat16* BsHi = (__nv_bfloat16*)(smem + OFF_B_HI);
    __nv_bfloat16* BsLo = (__nv_bfloat16*)(smem + OFF_B_LO);

    wmma::fragment<wmma::accumulator, 16, 16, 16, float> acc[2][NFRAG];
#pragma unroll
    for (int mi = 0; mi < 2; mi++)
#pragma unroll
        for (int ni = 0; ni < NFRAG; ni++) wmma::fill_fragment(acc[mi][ni], 0.f);

    const int nChunks = K >> 5;                       // BK = 32
    for (int kc = 0; kc < nChunks; kc++) {
        const int kOff = kc * 32;
        // A: 128 rows x 32 bf16 -> 4 uint4/row, 512 uint4, 2 per thread
#pragma unroll
        for (int i = 0; i < 2; i++) {
            int t = tid + 256 * i;
            int r = t >> 2, cq = t & 3;
            *(uint4*)(AsHi + r * LDS + cq * 8) =
                *(const uint4*)(aHi + (long)(bm + r) * lda + kOff + cq * 8);
            *(uint4*)(AsLo + r * LDS + cq * 8) =
                *(const uint4*)(aLo + (long)(bm + r) * lda + kOff + cq * 8);
        }
        // B: BN rows x 32 bf16
#pragma unroll
        for (int i = 0; i < BN / 64; i++) {
            int t = tid + 256 * i;
            int r = t >> 2, cq = t & 3;
            *(uint4*)(BsHi + r * LDS + cq * 8) =
                *(const uint4*)(bHi + (long)(bn + r) * ldb + kOff + cq * 8);
            *(uint4*)(BsLo + r * LDS + cq * 8) =
                *(const uint4*)(bLo + (long)(bn + r) * ldb + kOff + cq * 8);
        }
        __syncthreads();

#pragma unroll
        for (int kf = 0; kf < 32; kf += 16) {
            wmma::fragment<wmma::matrix_a, 16, 16, 16, __nv_bfloat16, wmma::row_major> aH[2], aL[2];
#pragma unroll
            for (int mi = 0; mi < 2; mi++) {
                wmma::load_matrix_sync(aH[mi], AsHi + (wm + mi * 16) * LDS + kf, LDS);
                wmma::load_matrix_sync(aL[mi], AsLo + (wm + mi * 16) * LDS + kf, LDS);
            }
#pragma unroll
            for (int ni = 0; ni < NFRAG; ni++) {
                wmma::fragment<wmma::matrix_b, 16, 16, 16, __nv_bfloat16, wmma::col_major> bH, bL;
                wmma::load_matrix_sync(bH, BsHi + (wn + ni * 16) * LDS + kf, LDS);
                wmma::load_matrix_sync(bL, BsLo + (wn + ni * 16) * LDS + kf, LDS);
#pragma unroll
                for (int mi = 0; mi < 2; mi++) {
                    wmma::mma_sync(acc[mi][ni], aH[mi], bH, acc[mi][ni]);
                    wmma::mma_sync(acc[mi][ni], aH[mi], bL, acc[mi][ni]);
                    wmma::mma_sync(acc[mi][ni], aL[mi], bH, acc[mi][ni]);
                }
            }
        }
        __syncthreads();
    }

    // ---- epilogue: frags -> smem C -> bias/alpha/(split) global -------------
    float* Cs = (float*)(smem + OFF_C);
#pragma unroll
    for (int mi = 0; mi < 2; mi++)
#pragma unroll
        for (int ni = 0; ni < NFRAG; ni++)
            wmma::store_matrix_sync(Cs + (wm + mi * 16) * BN + wn + ni * 16,
                                    acc[mi][ni], BN, wmma::mem_row_major);
    __syncthreads();

    const float* bs = (const float*)(smem + OFF_BIAS);
    constexpr int NV = 128 * BN / 4 / 256;            // float4s per thread
#pragma unroll
    for (int i = 0; i < NV; i++) {
        int t = tid + 256 * i;
        int r = t / (BN / 4);
        int c4 = t % (BN / 4);
        float4 v = *(float4*)(Cs + r * BN + c4 * 4);
        v.x = (v.x + bs[c4 * 4 + 0]) * alpha;
        v.y = (v.y + bs[c4 * 4 + 1]) * alpha;
        v.z = (v.z + bs[c4 * 4 + 2]) * alpha;
        v.w = (v.w + bs[c4 * 4 + 3]) * alpha;
        const long off = (long)(bm + r) * ldc + (long)z * cz + bn + c4 * 4;
        if (SPLIT_OUT) split_store4(cHi + off, cLo + off, v);
        else           *(float4*)(cF + off) = v;
    }
}

// ---------------------------------------------------------------------------
// Attention core (SIMT fp32, packed f32x2): one CTA per batch.
// ctx (35x512 = 70KB) staged once in smem; w written as SPLIT bf16.
// ---------------------------------------------------------------------------
typedef unsigned long long uu64;
__device__ __forceinline__ uu64 pack2(float x, float y) {
    uu64 r; asm("mov.b64 %0, {%1, %2};" : "=l"(r) : "f"(x), "f"(y)); return r;
}
__device__ __forceinline__ void fma2(uu64& d, uu64 a, uu64 b) {
    asm("fma.rn.f32x2 %0, %1, %2, %0;" : "+l"(d) : "l"(a), "l"(b));
}
__device__ __forceinline__ float2 unpack2(uu64 v) {
    float2 f; asm("mov.b64 {%0, %1}, %2;" : "=f"(f.x), "=f"(f.y) : "l"(v)); return f;
}

__global__ void __launch_bounds__(256)
attn_core(const float* __restrict__ qt, const float* __restrict__ cc,
          const float* __restrict__ hv, const float* __restrict__ ev,
          const float* __restrict__ sv,
          __nv_bfloat16* __restrict__ whi, __nv_bfloat16* __restrict__ wlo)
{
    extern __shared__ __align__(16) float smbuf[];
    float* ctx   = smbuf;                    // [35][512]
    float* sc    = smbuf + KCTX * DIM;       // [8][35]
    float* attnw = sc + HEADS * KCTX;        // [8][35]

    const int n    = blockIdx.x;
    const int tid  = threadIdx.x;
    const int lane = tid & 31;
    const int warp = tid >> 5;

    {
        const float4* c4 = (const float4*)(cc + (long)n * 32 * DIM);
        float4* d4 = (float4*)ctx;
#pragma unroll 4
        for (int i = tid; i < 32 * DIM / 4; i += 256) d4[i] = c4[i];
        for (int i = tid; i < 3 * DIM / 4; i += 256) {
            const int r = i >> 7;
            const int v = i & 127;
            const float* src = (r == 0) ? hv : (r == 1) ? ev : sv;
            ((float4*)(ctx + (32 + r) * DIM))[v] =
                ((const float4*)(src + (long)n * DIM))[v];
        }
    }
    __syncthreads();

    const int hp = warp >> 1;
    const int h0 = hp * 2, h1 = h0 + 1;

    // Phase B: scores
    {
        const float4* qa = (const float4*)(qt + (long)n * (HEADS * DIM) + h0 * DIM);
        const float4* qb = (const float4*)(qt + (long)n * (HEADS * DIM) + h1 * DIM);
        uu64 qa2[8], qb2[8];
#pragma unroll
        for (int i = 0; i < 4; i++) {
            float4 ra = qa[lane + 32 * i];
            float4 rb = qb[lane + 32 * i];
            qa2[2 * i] = pack2(ra.x, ra.y); qa2[2 * i + 1] = pack2(ra.z, ra.w);
            qb2[2 * i] = pack2(rb.x, rb.y); qb2[2 * i + 1] = pack2(rb.z, rb.w);
        }
        const int jg = warp & 1;
        const int jb = jg ? 18 : 0;
        const int je = jg ? KCTX : 18;
        for (int j = jb; j < je; j++) {
            const ulonglong2* xp = (const ulonglong2*)(ctx + j * DIM);
            uu64 p0 = 0ull, p1 = 0ull;
#pragma unroll
            for (int i = 0; i < 4; i++) {
                ulonglong2 x = xp[lane + 32 * i];
                fma2(p0, qa2[2 * i], x.x); fma2(p0, qa2[2 * i + 1], x.y);
                fma2(p1, qb2[2 * i], x.x); fma2(p1, qb2[2 * i + 1], x.y);
            }
            float2 f0 = unpack2(p0), f1 = unpack2(p1);
            float s0 = f0.x + f0.y, s1 = f1.x + f1.y;
#pragma unroll
            for (int o = 16; o; o >>= 1) {
                s0 += __shfl_xor_sync(0xffffffffu, s0, o);
                s1 += __shfl_xor_sync(0xffffffffu, s1, o);
            }
            if (lane == 0) { sc[h0 * KCTX + j] = s0; sc[h1 * KCTX + j] = s1; }
        }
    }
    __syncthreads();

    // Softmax
    {
        const int hh = warp;
        float s1 = sc[hh * KCTX + lane];
        float s2 = (lane < 3) ? sc[hh * KCTX + 32 + lane] : -3.0e38f;
        float m = fmaxf(s1, s2);
#pragma unroll
        for (int o = 16; o; o >>= 1)
            m = fmaxf(m, __shfl_xor_sync(0xffffffffu, m, o));
        float e1 = expf(s1 - m);
        float e2 = (lane < 3) ? expf(s2 - m) : 0.f;
        float sum = e1 + e2;
#pragma unroll
        for (int o = 16; o; o >>= 1)
            sum += __shfl_xor_sync(0xffffffffu, sum, o);
        float inv = 1.f / sum;
        attnw[hh * KCTX + lane] = e1 * inv;
        if (lane < 3) attnw[hh * KCTX + 32 + lane] = e2 * inv;
    }
    __syncthreads();

    // Phase C: w = attn @ ctx  -> split bf16 out
    {
        const int dh    = warp & 1;
        const int dbase = dh * 256;
        uu64 acc2[2][4];
#pragma unroll
        for (int hI = 0; hI < 2; hI++)
#pragma unroll
            for (int p = 0; p < 4; p++) acc2[hI][p] = 0ull;

        for (int j = 0; j < KCTX; j++) {
            const ulonglong2* xp = (const ulonglong2*)(ctx + j * DIM + dbase);
            uu64 a0d = pack2(attnw[h0 * KCTX + j], attnw[h0 * KCTX + j]);
            uu64 a1d = pack2(attnw[h1 * KCTX + j], attnw[h1 * KCTX + j]);
#pragma unroll
            for (int i = 0; i < 2; i++) {
                ulonglong2 x = xp[lane + 32 * i];
                fma2(acc2[0][2 * i], a0d, x.x); fma2(acc2[0][2 * i + 1], a0d, x.y);
                fma2(acc2[1][2 * i], a1d, x.x); fma2(acc2[1][2 * i + 1], a1d, x.y);
            }
        }
        const long w0off = (long)n * (HEADS * DIM) + h0 * DIM + dbase;
        const long w1off = (long)n * (HEADS * DIM) + h1 * DIM + dbase;
#pragma unroll
        for (int i = 0; i < 2; i++) {
            float2 a = unpack2(acc2[0][2 * i]);
            float2 b = unpack2(acc2[0][2 * i + 1]);
            split_store4(whi + w0off + 4 * (lane + 32 * i),
                         wlo + w0off + 4 * (lane + 32 * i),
                         make_float4(a.x, a.y, b.x, b.y));
            float2 c0 = unpack2(acc2[1][2 * i]);
            float2 d0 = unpack2(acc2[1][2 * i + 1]);
            split_store4(whi + w1off + 4 * (lane + 32 * i),
                         wlo + w1off + 4 * (lane + 32 * i),
                         make_float4(c0.x, c0.y, d0.x, d0.y));
        }
    }
}

// ---------------------------------------------------------------------------
// relu + LayerNorm (ddof=1, eps added to STD). One warp per row.
// ---------------------------------------------------------------------------
__global__ void __launch_bounds__(256)
relu_ln(const float* __restrict__ y, const float* __restrict__ ln_a,
        const float* __restrict__ ln_b, float* __restrict__ out)
{
    const int lane = threadIdx.x & 31;
    const int warp = threadIdx.x >> 5;
    const int row  = blockIdx.x * 8 + warp;

    const float4* xr = (const float4*)(y + (long)row * DIM);
    float4 v[4];
    float sum = 0.f;
#pragma unroll
    for (int i = 0; i < 4; i++) {
        float4 x = xr[lane + 32 * i];
        x.x = fmaxf(x.x, 0.f); x.y = fmaxf(x.y, 0.f);
        x.z = fmaxf(x.z, 0.f); x.w = fmaxf(x.w, 0.f);
        v[i] = x;
        sum += x.x + x.y + x.z + x.w;
    }
#pragma unroll
    for (int o = 16; o; o >>= 1) sum += __shfl_xor_sync(0xffffffffu, sum, o);
    const float mean = sum * (1.f / (float)DIM);

    float ssq = 0.f;
#pragma unroll
    for (int i = 0; i < 4; i++) {
        float dx;
        dx = v[i].x - mean; ssq = fmaf(dx, dx, ssq);
        dx = v[i].y - mean; ssq = fmaf(dx, dx, ssq);
        dx = v[i].z - mean; ssq = fmaf(dx, dx, ssq);
        dx = v[i].w - mean; ssq = fmaf(dx, dx, ssq);
    }
#pragma unroll
    for (int o = 16; o; o >>= 1) ssq += __shfl_xor_sync(0xffffffffu, ssq, o);
    const float stddev = sqrtf(ssq * (1.f / (float)(DIM - 1)));
    const float inv = 1.f / (stddev + 1e-6f);

    float4* orow = (float4*)(out + (long)row * DIM);
    const float4* a4 = (const float4*)ln_a;
    const float4* b4 = (const float4*)ln_b;
#pragma unroll
    for (int i = 0; i < 4; i++) {
        const int idx = lane + 32 * i;
        float4 a = a4[idx], b = b4[idx], o4;
        o4.x = fmaf(a.x * inv, v[i].x - mean, b.x);
        o4.y = fmaf(a.y * inv, v[i].y - mean, b.y);
        o4.z = fmaf(a.z * inv, v[i].z - mean, b.z);
        o4.w = fmaf(a.w * inv, v[i].w - mean, b.w);
        orow[idx] = o4;
    }
}

// ---------------------------------------------------------------------------
extern "C" void kernel_launch(void* const* d_in, const int* in_sizes, int n_in,
                              void* d_out, int out_size)
{
    const float* c   = (const float*)d_in[0];
    const float* h   = (const float*)d_in[1];
    const float* e   = (const float*)d_in[2];
    const float* s   = (const float*)d_in[3];
    const float* Wq  = (const float*)d_in[4];
    const float* bq  = (const float*)d_in[5];
    const float* Wk  = (const float*)d_in[6];
    /* bk = d_in[7] unused: constant across softmax axis, drops exactly */
    const float* Wv  = (const float*)d_in[8];
    const float* bv  = (const float*)d_in[9];
    const float* Wo  = (const float*)d_in[10];
    const float* bo  = (const float*)d_in[11];
    const float* la  = (const float*)d_in[12];
    const float* lb  = (const float*)d_in[13];
    float* out = (float*)d_out;

    void *p;
    __nv_bfloat16 *hHi, *hLo, *wqHi, *wqLo, *wkHi, *wkLo, *wvHi, *wvLo, *woHi, *woLo;
    __nv_bfloat16 *qpHi, *qpLo, *wHi, *wLo, *oHi, *oLo;
    float *qt, *y;
    cudaGetSymbolAddress(&p, g_h_hi);  hHi  = (__nv_bfloat16*)p;
    cudaGetSymbolAddress(&p, g_h_lo);  hLo  = (__nv_bfloat16*)p;
    cudaGetSymbolAddress(&p, g_wq_hi); wqHi = (__nv_bfloat16*)p;
    cudaGetSymbolAddress(&p, g_wq_lo); wqLo = (__nv_bfloat16*)p;
    cudaGetSymbolAddress(&p, g_wkT_hi); wkHi = (__nv_bfloat16*)p;
    cudaGetSymbolAddress(&p, g_wkT_lo); wkLo = (__nv_bfloat16*)p;
    cudaGetSymbolAddress(&p, g_wv_hi); wvHi = (__nv_bfloat16*)p;
    cudaGetSymbolAddress(&p, g_wv_lo); wvLo = (__nv_bfloat16*)p;
    cudaGetSymbolAddress(&p, g_wo_hi); woHi = (__nv_bfloat16*)p;
    cudaGetSymbolAddress(&p, g_wo_lo); woLo = (__nv_bfloat16*)p;
    cudaGetSymbolAddress(&p, g_qp_hi); qpHi = (__nv_bfloat16*)p;
    cudaGetSymbolAddress(&p, g_qp_lo); qpLo = (__nv_bfloat16*)p;
    cudaGetSymbolAddress(&p, g_qt);    qt   = (float*)p;
    cudaGetSymbolAddress(&p, g_w_hi);  wHi  = (__nv_bfloat16*)p;
    cudaGetSymbolAddress(&p, g_w_lo);  wLo  = (__nv_bfloat16*)p;
    cudaGetSymbolAddress(&p, g_o_hi);  oHi  = (__nv_bfloat16*)p;
    cudaGetSymbolAddress(&p, g_o_lo);  oLo  = (__nv_bfloat16*)p;
    cudaGetSymbolAddress(&p, g_y);     y    = (float*)p;

    // smem sizes: 1024 + max(A/B tiles, C overlay)
    const int SM128 = 1024 + ((2 * 128 * 40 * 2 + 2 * 128 * 40 * 2) > (128 * 128 * 4)
                              ? (2 * 128 * 40 * 2 + 2 * 128 * 40 * 2) : (128 * 128 * 4));
    const int SM64  = 1024 + ((2 * 128 * 40 * 2 + 2 * 64 * 40 * 2) > (128 * 64 * 4)
                              ? (2 * 128 * 40 * 2 + 2 * 64 * 40 * 2) : (128 * 64 * 4));
    const int ATTN_SMEM = (KCTX * DIM + 2 * HEADS * KCTX) * (int)sizeof(float);

    cudaFuncSetAttribute(wmmaGemm<128, true>,
                         cudaFuncAttributeMaxDynamicSharedMemorySize, SM128);
    cudaFuncSetAttribute(wmmaGemm<128, false>,
                         cudaFuncAttributeMaxDynamicSharedMemorySize, SM128);
    cudaFuncSetAttribute(wmmaGemm<64, true>,
                         cudaFuncAttributeMaxDynamicSharedMemorySize, SM64);
    cudaFuncSetAttribute(attn_core,
                         cudaFuncAttributeMaxDynamicSharedMemorySize, ATTN_SMEM);

    // 0) conversions
    splitF32<<<NB * DIM / 4 / 256, 256>>>(h, hHi, hLo);
    splitF32<<<DIM * DIM / 4 / 256, 256>>>(Wq, wqHi, wqLo);
    splitF32<<<DIM * DIM / 4 / 256, 256>>>(Wv, wvHi, wvLo);
    splitF32<<<DIM * DIM / 4 / 256, 256>>>(Wo, woHi, woLo);
    splitWkT<<<DIM * DIM / 256, 256>>>(Wk, wkHi, wkLo);

    // 1) qp = (h @ Wq^T + bq)*0.125 -> split bf16
    wmmaGemm<128, true><<<dim3(4, 64, 1), 256, SM128>>>(
        hHi, hLo, DIM, 0, wqHi, wqLo, DIM, 0, bq, 0,
        (float*)0, qpHi, qpLo, DIM, 0, DIM, 0.125f);

    // 2) qt[n, h*512+d] = qp_h @ WkT_h^T  (z = head, K = 64) -> fp32
    wmmaGemm<128, false><<<dim3(4, 64, 8), 256, SM128>>>(
        qpHi, qpLo, DIM, 64, wkHi, wkLo, 64, 512 * 64, (const float*)0, 0,
        qt, (__nv_bfloat16*)0, (__nv_bfloat16*)0, HEADS * DIM, DIM, 64, 1.0f);

    // 3) attention core -> w split bf16
    attn_core<<<NB, 256, ATTN_SMEM>>>(qt, c, h, e, s, wHi, wLo);

    // 4) o[:, h*64..] = w_h @ Wv_h^T + bv_h (z = head) -> split bf16
    wmmaGemm<64, true><<<dim3(1, 64, 8), 256, SM64>>>(
        wHi, wLo, HEADS * DIM, DIM, wvHi, wvLo, DIM, 64 * DIM, bv, 64,
        (float*)0, oHi, oLo, DIM, 64, DIM, 1.0f);

    // 5) y = o @ Wo^T + bo -> fp32
    wmmaGemm<128, false><<<dim3(4, 64, 1), 256, SM128>>>(
        oHi, oLo, DIM, 0, woHi, woLo, DIM, 0, bo, 0,
        y, (__nv_bfloat16*)0, (__nv_bfloat16*)0, DIM, 0, DIM, 1.0f);

    // 6) out = LN(relu(y))
    relu_ln<<<NB / 8, 256>>>(y, la, lb, out);
}